// round 12
// baseline (speedup 1.0000x reference)
#include <cuda_runtime.h>
#include <cuda_fp16.h>
#include <math.h>
#include <stdint.h>

// Problem constants
#define BB   256
#define TT   256
#define II   256
#define HH   1024
#define KTOT 1280
#define NG   4096
#define TAUc 0.05f
#define MHUc 1.5f
#define BTH  ((long)BB * TT * HH)
#define BH   ((long)BB * HH)

// Grid (64 ctan, 2 mtile) = 128 CTAs, persistent 1/SM, 512 threads = 16 warps.
// Two independent 8-warp halves split along K: half h does global BK=64 stages
// g = 2j + h (j = 0..9). Each half: warp tile 32x32 (4m x 2n), own smem ring.
#define NKT    40          // 32-k images (KTOT/32)
#define XKT    8           // x images per (t, mt)
#define NSTH   10          // stages per half (20 global BK=64 stages)
#define STAGES 4           // ring slots per half
#define A_IMG  2048        // uint32 per 32-k A image (128 rows x 32 k fp16)
#define B_IMG  1024        // uint32 per 32-k B image (64 n x 32 k fp16)
// slot = A 1024 uint4 (16KB) + B 512 uint4 (8KB) = 24KB = 1536 uint4
#define SLOT_U4   1536
#define RING_U4   (STAGES * SLOT_U4)        // 6144 uint4 = 96KB per half
#define XBUF_U4   2048                      // 32KB acc exchange
#define DSMEM     ((2 * RING_U4 + XBUF_U4) * 16)   // 229376 B = 224KB

// ---------------------------------------------------------------------------
// Persistent scratch (unchanged layouts from R10/R11).
// A image: [mb(8)][kb16(2)][lane(32)][reg(4)] uint32 (128 rows x 32 k):
//   reg j, half h: row' = (lane>>2) + 8*(j&1), k' = (lane&3)*2 + 8*(j>>1) + h
// B image: [nbp(4)][kb16(2)][lane(32)][j(4)] uint32:
//   nb = nbp*2 + (j>>1), r = j&1: k = r*8 + (lane&3)*2 + h, n = nb*8 + (lane>>2)
// ---------------------------------------------------------------------------
__device__ uint32_t g_xp[(long)TT * 2 * XKT * A_IMG];
__device__ uint32_t g_hp[2][2 * 32 * A_IMG];
__device__ uint32_t g_Wp[(long)64 * NKT * B_IMG];
__device__ float    g_c[BB * HH];
__device__ unsigned g_bar[2];              // per-mtile phase barriers (monotonic)

__device__ __forceinline__ float tanh_fast(float x) {
    float r;
    asm("tanh.approx.f32 %0, %1;" : "=f"(r) : "f"(x));
    return r;
}
__device__ __forceinline__ float sig_fast(float x) {
    return 0.5f * tanh_fast(0.5f * x) + 0.5f;
}

// ---------------------------------------------------------------------------
// Column permutation: permuted col n -> gate = (n>>3)&3,
//   hcol = ((n>>6)<<4) | (((n>>5)&1)<<3) | (n&7)
// ---------------------------------------------------------------------------
__global__ void transform_x(const float* __restrict__ x) {
    uint32_t p = blockIdx.x * blockDim.x + threadIdx.x;   // 8,388,608 total
    int j    = p & 3;
    int lane = (p >> 2) & 31;
    int kb   = (p >> 7) & 1;
    int mb   = (p >> 8) & 7;
    int kt   = (p >> 11) & 7;
    int mt   = (p >> 14) & 1;
    int t    = p >> 15;
    int rowp = (lane >> 2) + 8 * (j & 1);
    int kp   = (lane & 3) * 2 + 8 * (j >> 1);
    int b    = mt * 128 + mb * 16 + rowp;
    int i    = kt * 32 + kb * 16 + kp;
    const float* src = x + ((long)b * TT + t) * II + i;
    __half2 v = __floats2half2_rn(src[0], src[1]);
    g_xp[p] = *(uint32_t*)&v;
}

__global__ void transform_W(const float* __restrict__ Wx, const float* __restrict__ Wh) {
    uint32_t p = blockIdx.x * blockDim.x + threadIdx.x;
    if (p >= (uint32_t)64 * NKT * B_IMG) return;
    int j    = p & 3;
    int lane = (p >> 2) & 31;
    int kb   = (p >> 7) & 1;
    int nbp  = (p >> 8) & 3;
    int kt   = (int)((p >> 10) % NKT);
    int ctan = (int)((p >> 10) / NKT);
    int nb   = nbp * 2 + (j >> 1);
    int r    = j & 1;
    int n    = ctan * 64 + nb * 8 + (lane >> 2);
    int gate = (n >> 3) & 3;
    int hcol = ((n >> 6) << 4) | (((n >> 5) & 1) << 3) | (n & 7);
    int col  = gate * HH + hcol;
    int kg   = kt * 32 + kb * 16 + r * 8 + (lane & 3) * 2;
    float v0 = (kg < II)     ? Wx[(long)kg * NG + col]       : Wh[(long)(kg - II) * NG + col];
    float v1 = (kg + 1 < II) ? Wx[(long)(kg + 1) * NG + col] : Wh[(long)(kg + 1 - II) * NG + col];
    __half2 v = __floats2half2_rn(v0, v1);
    g_Wp[p] = *(uint32_t*)&v;
}

__global__ void init_state(const float* __restrict__ h0, const float* __restrict__ c0) {
    uint32_t p = blockIdx.x * blockDim.x + threadIdx.x;
    if (p < 2) g_bar[p] = 0u;
    if (p >= 262144) return;
    if (p < 131072) {   // h0 -> packed A images
        int j    = p & 3;
        int lane = (p >> 2) & 31;
        int kb   = (p >> 7) & 1;
        int mb   = (p >> 8) & 7;
        int hkt  = (p >> 11) & 31;
        int mt   = (p >> 16) & 1;
        int rowp = (lane >> 2) + 8 * (j & 1);
        int kp   = (lane & 3) * 2 + 8 * (j >> 1);
        int b    = mt * 128 + mb * 16 + rowp;
        int hc   = hkt * 32 + kb * 16 + kp;
        __half2 v = __floats2half2_rn(h0[b * HH + hc], h0[b * HH + hc + 1]);
        g_hp[0][p] = *(uint32_t*)&v;
    }
    g_c[p] = c0[p];
}

// ---------------------------------------------------------------------------
__device__ __forceinline__ void cp16(uint32_t saddr, const void* g) {
    asm volatile("cp.async.cg.shared.global [%0], [%1], 16;\n" :: "r"(saddr), "l"(g));
}
#define CP_COMMIT() asm volatile("cp.async.commit_group;\n" ::: "memory")
#define CP_WAIT(N)  asm volatile("cp.async.wait_group %0;\n" :: "n"(N) : "memory")
#define BARX(id, n) asm volatile("bar.sync %0, %1;" :: "r"(id), "r"(n) : "memory")

__device__ __forceinline__ void bar_arrive(unsigned* a) {
    asm volatile("red.release.gpu.global.add.u32 [%0], 1;" :: "l"(a) : "memory");
}
__device__ __forceinline__ unsigned bar_poll(const unsigned* a) {
    unsigned v;
    asm volatile("ld.acquire.gpu.global.u32 %0, [%1];" : "=r"(v) : "l"(a) : "memory");
    return v;
}

__device__ __forceinline__ void mma16816(float* d, const uint4& a, uint32_t b0, uint32_t b1) {
    asm volatile(
        "mma.sync.aligned.m16n8k16.row.col.f32.f16.f16.f32 "
        "{%0,%1,%2,%3}, {%4,%5,%6,%7}, {%8,%9}, {%0,%1,%2,%3};"
        : "+f"(d[0]), "+f"(d[1]), "+f"(d[2]), "+f"(d[3])
        : "r"(a.x), "r"(a.y), "r"(a.z), "r"(a.w), "r"(b0), "r"(b1));
}

// ---------------------------------------------------------------------------
// Persistent kernel: 256 timesteps; per CTA two K-split 8-warp pipelines.
// ---------------------------------------------------------------------------
__global__ void __launch_bounds__(512, 1)
lstm_persist(const float* __restrict__ bias,   // (4H,)
             float* __restrict__ out)          // outputs | hN | cN
{
    extern __shared__ uint4 smem[];

    const int tid    = threadIdx.x;
    const int lane   = tid & 31;
    const int half   = tid >> 8;         // 0 = pipeline A, 1 = pipeline B
    const int htid   = tid & 255;
    const int warp   = htid >> 5;        // 0..7 within half
    const int warp_m = warp >> 1;        // 0..3 (32 rows)
    const int warp_n = warp & 1;         // 0..1 (32 cols)
    const int ctan   = blockIdx.x;       // 0..63
    const int mt     = blockIdx.y;       // 0..1

    uint4* ring  = smem + half * RING_U4;
    uint4* xbuf  = smem + 2 * RING_U4;   // 32KB acc exchange (half B -> half A)
    const uint32_t ring_b = (uint32_t)__cvta_generic_to_shared(ring);
    const int mybarrier = 1 + half;      // named barrier id for this half

    const int hbase = ctan * 16 + warp_n * 8 + 2 * (lane & 3);

    float bg0[4], bg1[4];
    #pragma unroll
    for (int g = 0; g < 4; g++) {
        bg0[g] = __ldg(bias + g * HH + hbase);
        bg1[g] = __ldg(bias + g * HH + hbase + 1);
    }

    unsigned* mybar = &g_bar[mt];

    for (int t = 0; t < TT; t++) {
        const int srcbuf = t & 1;
        const uint32_t* __restrict__ hsrc = g_hp[srcbuf];
        uint32_t*       __restrict__ hdst = g_hp[srcbuf ^ 1];

        // half A carries the bias; half B starts from zero (pure partial sum)
        float acc[2][4][4];
        #pragma unroll
        for (int g = 0; g < 4; g++) {
            float a0 = half ? 0.0f : bg0[g];
            float a1 = half ? 0.0f : bg1[g];
            #pragma unroll
            for (int mb = 0; mb < 2; mb++) {
                acc[mb][g][0] = a0; acc[mb][g][1] = a1;
                acc[mb][g][2] = a0; acc[mb][g][3] = a1;
            }
        }

        // local stage j -> global BK=64 stage g = 2j + half -> 32k images 2g, 2g+1
        auto issue = [&](int j) {
            int s = j & (STAGES - 1);
            int g = 2 * j + half;
            const uint32_t* asrc = (g < 4)
                ? g_xp + ((long)(t * 2 + mt) * XKT + g * 2) * A_IMG
                : hsrc + (long)(mt * 32 + (g - 4) * 2) * A_IMG;
            const uint32_t* bsrc = g_Wp + ((long)ctan * NKT + g * 2) * B_IMG;
            #pragma unroll
            for (int r = 0; r < 4; r++) {
                int idx = htid + 256 * r;
                cp16(ring_b + (uint32_t)(s * SLOT_U4 + idx) * 16, asrc + idx * 4);
            }
            #pragma unroll
            for (int r = 0; r < 2; r++) {
                int idx = htid + 256 * r;
                cp16(ring_b + (uint32_t)(s * SLOT_U4 + 1024 + idx) * 16, bsrc + idx * 4);
            }
        };

        // x prologue (local stages 0,1 -> global 0..3 are x-only) hides the spin
        issue(0); CP_COMMIT();
        issue(1); CP_COMMIT();

        if (t > 0) {
            if (htid == 0) {
                unsigned target = (unsigned)(64 * t);
                while (bar_poll(mybar) < target) { }
            }
            BARX(mybarrier, 256);
        }
        issue(2); CP_COMMIT();

        for (int j = 0; j < NSTH; j++) {
            CP_WAIT(2);
            BARX(mybarrier, 256);

            int s = j & (STAGES - 1);
            const uint4* A  = ring + s * SLOT_U4;
            const uint4* Bm = ring + s * SLOT_U4 + 1024;

            #pragma unroll
            for (int kk = 0; kk < 4; kk++) {   // 4 k16 chunks per BK=64 stage
                uint4 af0 = A[(kk >> 1) * 512 + ((warp_m * 2 + 0) * 2 + (kk & 1)) * 32 + lane];
                uint4 af1 = A[(kk >> 1) * 512 + ((warp_m * 2 + 1) * 2 + (kk & 1)) * 32 + lane];
                uint4 bf0 = Bm[(kk >> 1) * 256 + ((warp_n * 2 + 0) * 2 + (kk & 1)) * 32 + lane];
                uint4 bf1 = Bm[(kk >> 1) * 256 + ((warp_n * 2 + 1) * 2 + (kk & 1)) * 32 + lane];
                mma16816(acc[0][0], af0, bf0.x, bf0.y);
                mma16816(acc[0][1], af0, bf0.z, bf0.w);
                mma16816(acc[0][2], af0, bf1.x, bf1.y);
                mma16816(acc[0][3], af0, bf1.z, bf1.w);
                mma16816(acc[1][0], af1, bf0.x, bf0.y);
                mma16816(acc[1][1], af1, bf0.z, bf0.w);
                mma16816(acc[1][2], af1, bf1.x, bf1.y);
                mma16816(acc[1][3], af1, bf1.z, bf1.w);
            }

            if (j + 3 < NSTH) issue(j + 3);   // slot (j-1)&3: readers passed bar above
            CP_COMMIT();
        }

        // ---- combine: half B publishes partial acc, half A finishes --------
        if (half) {
            const float* a = &acc[0][0][0];
            #pragma unroll
            for (int i = 0; i < 8; i++)
                xbuf[htid * 8 + i] = *(const uint4*)(a + i * 4);
        }
        BARX(0, 512);   // full-CTA: xbuf visible to half A

        if (!half) {
            float* a = &acc[0][0][0];
            #pragma unroll
            for (int i = 0; i < 8; i++) {
                uint4 v = xbuf[htid * 8 + i];
                a[i * 4 + 0] += __uint_as_float(v.x);
                a[i * 4 + 1] += __uint_as_float(v.y);
                a[i * 4 + 2] += __uint_as_float(v.z);
                a[i * 4 + 3] += __uint_as_float(v.w);
            }

            // ---- epilogue (half A only) ------------------------------------
            #pragma unroll
            for (int mb = 0; mb < 2; mb++) {
                #pragma unroll
                for (int hf = 0; hf < 2; hf++) {
                    int m_loc = warp_m * 32 + mb * 16 + (lane >> 2) + hf * 8;
                    int r = mt * 128 + m_loc;
                    long cidx = (long)r * HH + hbase;
                    float2 cold = *(const float2*)(g_c + cidx);
                    float hn[2], cn[2];
                    #pragma unroll
                    for (int j = 0; j < 2; j++) {
                        int c2 = hf * 2 + j;
                        float ii = sig_fast(acc[mb][0][c2]);
                        float ff = sig_fast(acc[mb][1][c2]);
                        float tg = tanh_fast(acc[mb][2][c2]);
                        float oo = sig_fast(acc[mb][3][c2]);
                        float cnew = ff * (j ? cold.y : cold.x) + ii * tg;
                        cn[j] = cnew;
                        hn[j] = oo * tanh_fast(cnew);
                    }
                    *(float2*)(g_c + cidx) = make_float2(cn[0], cn[1]);
                    *(float2*)(out + ((long)r * TT + t) * HH + hbase) = make_float2(hn[0], hn[1]);
                    if (t == TT - 1) {
                        *(float2*)(out + BTH + (long)r * HH + hbase)      = make_float2(hn[0], hn[1]);
                        *(float2*)(out + BTH + BH + (long)r * HH + hbase) = make_float2(cn[0], cn[1]);
                    }
                    float h0s = hn[0], h1s = hn[1];
                    if (hbase == 0) {
                        h0s = hn[0] + TAUc * (MHUc * hn[0] + hn[1] / MHUc);
                        h1s = hn[1] - TAUc * (MHUc * hn[0]);
                    }
                    int mbb  = m_loc >> 4;
                    int rowp = m_loc & 15;
                    int hkt  = hbase >> 5;
                    int kb   = (hbase >> 4) & 1;
                    int jj   = ((rowp >> 3) & 1) | ((((hbase & 15) >= 8) ? 1 : 0) << 1);
                    int lanep = ((rowp & 7) << 2) | ((hbase & 7) >> 1);
                    __half2 hv = __floats2half2_rn(h0s, h1s);
                    hdst[(long)(mt * 32 + hkt) * A_IMG + ((mbb * 2 + kb) * 32 + lanep) * 4 + jj] =
                        *(uint32_t*)&hv;
                }
            }

            if (t + 1 < TT) {
                BARX(1, 256);                  // half A's h stores all issued
                if (htid == 0) bar_arrive(mybar);
            }
        }
        // half B proceeds directly to the next step; its h-stage issue is gated
        // by the spin, which requires half A's arrive -> xbuf reuse is ordered.
    }
}

// ---------------------------------------------------------------------------
extern "C" void kernel_launch(void* const* d_in, const int* in_sizes, int n_in,
                              void* d_out, int out_size) {
    const float* x  = (const float*)d_in[0];
    const float* h0 = (const float*)d_in[1];
    const float* c0 = (const float*)d_in[2];
    const float* Wx = (const float*)d_in[3];
    const float* Wh = (const float*)d_in[4];
    const float* b  = (const float*)d_in[5];
    float* out = (float*)d_out;

    cudaFuncSetAttribute(lstm_persist, cudaFuncAttributeMaxDynamicSharedMemorySize, DSMEM);

    transform_x<<<32768, 256>>>(x);
    {
        long total = (long)64 * NKT * B_IMG;
        transform_W<<<(int)((total + 255) / 256), 256>>>(Wx, Wh);
    }
    init_state<<<1024, 256>>>(h0, c0);

    lstm_persist<<<dim3(64, 2), 512, DSMEM>>>(b, out);
}

// round 13
// speedup vs baseline: 1.2848x; 1.2848x over previous
#include <cuda_runtime.h>
#include <cuda_fp16.h>
#include <math.h>
#include <stdint.h>

// Problem constants
#define BB   256
#define TT   256
#define II   256
#define HH   1024
#define KTOT 1280
#define NG   4096
#define TAUc 0.05f
#define MHUc 1.5f
#define BTH  ((long)BB * TT * HH)
#define BH   ((long)BB * HH)

// Tiling: BM=128, BN=64, stage BK=128 (8 x k16). Grid (64 ctan, 2 mtile) = 128 CTAs,
// persistent (1/SM). 256 threads = 8 warps, 4m x 2n, warp tile 32x32.
#define NKT    40          // 32-k images (KTOT/32)
#define XKT    8           // x images per (t, mt)
#define NST    10          // stages per step (KTOT/128)
#define STAGES 4           // smem ring slots
#define A_IMG  2048        // uint32 per 32-k A image (128 rows x 32 k fp16)
#define B_IMG  1024        // uint32 per 32-k B image (64 n x 32 k fp16)
#define DSMEM  (STAGES * 3072 * 16)   // 192KB dynamic smem

// ---------------------------------------------------------------------------
// Persistent scratch (layouts unchanged from R10/R11).
// A image: [mb(8)][kb16(2)][lane(32)][reg(4)] uint32 (128 rows x 32 k):
//   reg j, half h: row' = (lane>>2) + 8*(j&1), k' = (lane&3)*2 + 8*(j>>1) + h
// B image: [nbp(4)][kb16(2)][lane(32)][j(4)] uint32:
//   nb = nbp*2 + (j>>1), r = j&1: k = r*8 + (lane&3)*2 + h, n = nb*8 + (lane>>2)
// ---------------------------------------------------------------------------
__device__ uint32_t g_xp[(long)TT * 2 * XKT * A_IMG];
__device__ uint32_t g_hp[2][2 * 32 * A_IMG];
__device__ uint32_t g_Wp[(long)64 * NKT * B_IMG];
__device__ float    g_c[BB * HH];
__device__ unsigned g_bar[2];              // per-mtile phase barriers (monotonic)

__device__ __forceinline__ float tanh_fast(float x) {
    float r;
    asm("tanh.approx.f32 %0, %1;" : "=f"(r) : "f"(x));
    return r;
}
__device__ __forceinline__ float sig_fast(float x) {
    return 0.5f * tanh_fast(0.5f * x) + 0.5f;
}

// ---------------------------------------------------------------------------
// Column permutation: permuted col n -> gate = (n>>3)&3,
//   hcol = ((n>>6)<<4) | (((n>>5)&1)<<3) | (n&7)
// ---------------------------------------------------------------------------
__global__ void transform_x(const float* __restrict__ x) {
    uint32_t p = blockIdx.x * blockDim.x + threadIdx.x;   // 8,388,608 total
    int j    = p & 3;
    int lane = (p >> 2) & 31;
    int kb   = (p >> 7) & 1;
    int mb   = (p >> 8) & 7;
    int kt   = (p >> 11) & 7;
    int mt   = (p >> 14) & 1;
    int t    = p >> 15;
    int rowp = (lane >> 2) + 8 * (j & 1);
    int kp   = (lane & 3) * 2 + 8 * (j >> 1);
    int b    = mt * 128 + mb * 16 + rowp;
    int i    = kt * 32 + kb * 16 + kp;
    const float* src = x + ((long)b * TT + t) * II + i;
    __half2 v = __floats2half2_rn(src[0], src[1]);
    g_xp[p] = *(uint32_t*)&v;
}

__global__ void transform_W(const float* __restrict__ Wx, const float* __restrict__ Wh) {
    uint32_t p = blockIdx.x * blockDim.x + threadIdx.x;
    if (p >= (uint32_t)64 * NKT * B_IMG) return;
    int j    = p & 3;
    int lane = (p >> 2) & 31;
    int kb   = (p >> 7) & 1;
    int nbp  = (p >> 8) & 3;
    int kt   = (int)((p >> 10) % NKT);
    int ctan = (int)((p >> 10) / NKT);
    int nb   = nbp * 2 + (j >> 1);
    int r    = j & 1;
    int n    = ctan * 64 + nb * 8 + (lane >> 2);
    int gate = (n >> 3) & 3;
    int hcol = ((n >> 6) << 4) | (((n >> 5) & 1) << 3) | (n & 7);
    int col  = gate * HH + hcol;
    int kg   = kt * 32 + kb * 16 + r * 8 + (lane & 3) * 2;
    float v0 = (kg < II)     ? Wx[(long)kg * NG + col]       : Wh[(long)(kg - II) * NG + col];
    float v1 = (kg + 1 < II) ? Wx[(long)(kg + 1) * NG + col] : Wh[(long)(kg + 1 - II) * NG + col];
    __half2 v = __floats2half2_rn(v0, v1);
    g_Wp[p] = *(uint32_t*)&v;
}

__global__ void init_state(const float* __restrict__ h0, const float* __restrict__ c0) {
    uint32_t p = blockIdx.x * blockDim.x + threadIdx.x;
    if (p < 2) g_bar[p] = 0u;
    if (p >= 262144) return;
    if (p < 131072) {   // h0 -> packed A images
        int j    = p & 3;
        int lane = (p >> 2) & 31;
        int kb   = (p >> 7) & 1;
        int mb   = (p >> 8) & 7;
        int hkt  = (p >> 11) & 31;
        int mt   = (p >> 16) & 1;
        int rowp = (lane >> 2) + 8 * (j & 1);
        int kp   = (lane & 3) * 2 + 8 * (j >> 1);
        int b    = mt * 128 + mb * 16 + rowp;
        int hc   = hkt * 32 + kb * 16 + kp;
        __half2 v = __floats2half2_rn(h0[b * HH + hc], h0[b * HH + hc + 1]);
        g_hp[0][p] = *(uint32_t*)&v;
    }
    g_c[p] = c0[p];
}

// ---------------------------------------------------------------------------
__device__ __forceinline__ void cp16(uint32_t saddr, const void* g) {
    asm volatile("cp.async.cg.shared.global [%0], [%1], 16;\n" :: "r"(saddr), "l"(g));
}
#define CP_COMMIT() asm volatile("cp.async.commit_group;\n" ::: "memory")
#define CP_WAIT(N)  asm volatile("cp.async.wait_group %0;\n" :: "n"(N) : "memory")

__device__ __forceinline__ void bar_arrive(unsigned* a) {
    asm volatile("red.release.gpu.global.add.u32 [%0], 1;" :: "l"(a) : "memory");
}
__device__ __forceinline__ unsigned bar_poll(const unsigned* a) {
    unsigned v;
    asm volatile("ld.acquire.gpu.global.u32 %0, [%1];" : "=r"(v) : "l"(a) : "memory");
    return v;
}

__device__ __forceinline__ void mma16816(float* d, const uint4& a, uint32_t b0, uint32_t b1) {
    asm volatile(
        "mma.sync.aligned.m16n8k16.row.col.f32.f16.f16.f32 "
        "{%0,%1,%2,%3}, {%4,%5,%6,%7}, {%8,%9}, {%0,%1,%2,%3};"
        : "+f"(d[0]), "+f"(d[1]), "+f"(d[2]), "+f"(d[3])
        : "r"(a.x), "r"(a.y), "r"(a.z), "r"(a.w), "r"(b0), "r"(b1));
}

// ---------------------------------------------------------------------------
// Persistent kernel: 256 timesteps; cross-step pipelined x-prologue; c in regs;
// out-stores moved past the inter-CTA arrive.
// ---------------------------------------------------------------------------
__global__ void __launch_bounds__(256, 1)
lstm_persist(const float* __restrict__ bias,   // (4H,)
             float* __restrict__ out)          // outputs | hN | cN
{
    extern __shared__ uint4 smem[];
    uint4* sA4 = smem;                      // [4][2048] uint4
    uint4* sB4 = smem + STAGES * 2048;      // [4][1024] uint4

    const int tid    = threadIdx.x;
    const int lane   = tid & 31;
    const int warp   = tid >> 5;
    const int warp_m = warp >> 1;        // 0..3 (32 rows)
    const int warp_n = warp & 1;         // 0..1 (32 cols)
    const int ctan   = blockIdx.x;       // 0..63
    const int mt     = blockIdx.y;       // 0..1

    const uint32_t sA_b = (uint32_t)__cvta_generic_to_shared(sA4);
    const uint32_t sB_b = (uint32_t)__cvta_generic_to_shared(sB4);

    const int hbase = ctan * 16 + warp_n * 8 + 2 * (lane & 3);

    float bg0[4], bg1[4];
    #pragma unroll
    for (int g = 0; g < 4; g++) {
        bg0[g] = __ldg(bias + g * HH + hbase);
        bg1[g] = __ldg(bias + g * HH + hbase + 1);
    }

    // cell state lives in registers for the whole sequence (thread-private)
    float creg[2][2][2];
    #pragma unroll
    for (int mb = 0; mb < 2; mb++)
        #pragma unroll
        for (int hf = 0; hf < 2; hf++) {
            int m_loc = warp_m * 32 + mb * 16 + (lane >> 2) + hf * 8;
            int r = mt * 128 + m_loc;
            float2 c0v = *(const float2*)(g_c + (long)r * HH + hbase);
            creg[mb][hf][0] = c0v.x;
            creg[mb][hf][1] = c0v.y;
        }

    unsigned* mybar = &g_bar[mt];

    // stage s of step tt -> ring slot (2*tt + s) & 3 (continuous counter)
    auto issue = [&](int tt, int s, int slot) {
        const uint32_t* asrc = (s < 2)
            ? g_xp + ((long)(tt * 2 + mt) * XKT + s * 4) * A_IMG
            : g_hp[tt & 1] + (long)(mt * 32 + (s - 2) * 4) * A_IMG;
        const uint32_t* bsrc = g_Wp + ((long)ctan * NKT + s * 4) * B_IMG;
        #pragma unroll
        for (int r = 0; r < 8; r++) {
            int idx = tid + 256 * r;
            cp16(sA_b + (uint32_t)(slot * 2048 + idx) * 16, asrc + idx * 4);
        }
        #pragma unroll
        for (int r = 0; r < 4; r++) {
            int idx = tid + 256 * r;
            cp16(sB_b + (uint32_t)(slot * 1024 + idx) * 16, bsrc + idx * 4);
        }
    };

    // t=0 x-prologue (later steps get their x stages issued inside step t-1)
    issue(0, 0, 0); CP_COMMIT();
    issue(0, 1, 1); CP_COMMIT();

    for (int t = 0; t < TT; t++) {
        const int phase = (2 * t) & 3;

        // wait for all mt-peers to publish h(t)
        if (t > 0) {
            if (tid == 0) {
                unsigned target = (unsigned)(64 * t);
                while (bar_poll(mybar) < target) { }
            }
            __syncthreads();
        }
        issue(t, 2, (phase + 2) & 3); CP_COMMIT();

        float acc[2][4][4];
        #pragma unroll
        for (int g = 0; g < 4; g++) {
            #pragma unroll
            for (int mb = 0; mb < 2; mb++) {
                acc[mb][g][0] = bg0[g]; acc[mb][g][1] = bg1[g];
                acc[mb][g][2] = bg0[g]; acc[mb][g][3] = bg1[g];
            }
        }

        for (int s = 0; s < NST; s++) {
            CP_WAIT(2);
            __syncthreads();

            int slot = (phase + s) & 3;
            const uint4* A  = sA4 + slot * 2048;
            const uint4* Bm = sB4 + slot * 1024;

            #pragma unroll
            for (int kk = 0; kk < 8; kk++) {   // 8 k16 chunks per stage
                uint4 af0 = A[(kk >> 1) * 512 + ((warp_m * 2 + 0) * 2 + (kk & 1)) * 32 + lane];
                uint4 af1 = A[(kk >> 1) * 512 + ((warp_m * 2 + 1) * 2 + (kk & 1)) * 32 + lane];
                uint4 bf0 = Bm[(kk >> 1) * 256 + ((warp_n * 2 + 0) * 2 + (kk & 1)) * 32 + lane];
                uint4 bf1 = Bm[(kk >> 1) * 256 + ((warp_n * 2 + 1) * 2 + (kk & 1)) * 32 + lane];
                mma16816(acc[0][0], af0, bf0.x, bf0.y);
                mma16816(acc[0][1], af0, bf0.z, bf0.w);
                mma16816(acc[0][2], af0, bf1.x, bf1.y);
                mma16816(acc[0][3], af0, bf1.z, bf1.w);
                mma16816(acc[1][0], af1, bf0.x, bf0.y);
                mma16816(acc[1][1], af1, bf0.z, bf0.w);
                mma16816(acc[1][2], af1, bf1.x, bf1.y);
                mma16816(acc[1][3], af1, bf1.z, bf1.w);
            }

            // issue-ahead: stage s+3 of this step, or next step's x stages
            int sn = s + 3;
            if (sn < NST) {
                issue(t, sn, (phase + sn) & 3);
            } else if (sn <= 11 && t + 1 < TT) {
                issue(t + 1, sn - 10, (phase + sn) & 3);
            }
            CP_COMMIT();   // exactly one commit per stage keeps group accounting
        }

        // ---- epilogue part 1: gate math, c update (regs), h-carry stores ----
        uint32_t* hdst = g_hp[(t & 1) ^ 1];
        float hnb[2][2][2];
        #pragma unroll
        for (int mb = 0; mb < 2; mb++) {
            #pragma unroll
            for (int hf = 0; hf < 2; hf++) {
                int m_loc = warp_m * 32 + mb * 16 + (lane >> 2) + hf * 8;
                float hn[2];
                #pragma unroll
                for (int j = 0; j < 2; j++) {
                    int c2 = hf * 2 + j;
                    float ii = sig_fast(acc[mb][0][c2]);
                    float ff = sig_fast(acc[mb][1][c2]);
                    float tg = tanh_fast(acc[mb][2][c2]);
                    float oo = sig_fast(acc[mb][3][c2]);
                    float cnew = ff * creg[mb][hf][j] + ii * tg;
                    creg[mb][hf][j] = cnew;
                    hn[j] = oo * tanh_fast(cnew);
                    hnb[mb][hf][j] = hn[j];
                }
                float h0s = hn[0], h1s = hn[1];
                if (hbase == 0) {
                    h0s = hn[0] + TAUc * (MHUc * hn[0] + hn[1] / MHUc);
                    h1s = hn[1] - TAUc * (MHUc * hn[0]);
                }
                int mbb  = m_loc >> 4;
                int rowp = m_loc & 15;
                int hkt  = hbase >> 5;
                int kb   = (hbase >> 4) & 1;
                int jj   = ((rowp >> 3) & 1) | ((((hbase & 15) >= 8) ? 1 : 0) << 1);
                int lanep = ((rowp & 7) << 2) | ((hbase & 7) >> 1);
                __half2 hv = __floats2half2_rn(h0s, h1s);
                hdst[(long)(mt * 32 + hkt) * A_IMG + ((mbb * 2 + kb) * 32 + lanep) * 4 + jj] =
                    *(uint32_t*)&hv;
            }
        }

        // publish h(t+1 inputs) EARLY, before the out stores
        if (t + 1 < TT) {
            __syncthreads();
            if (tid == 0) bar_arrive(mybar);
        }

        // ---- epilogue part 2: output stores (off the inter-CTA path) --------
        #pragma unroll
        for (int mb = 0; mb < 2; mb++) {
            #pragma unroll
            for (int hf = 0; hf < 2; hf++) {
                int m_loc = warp_m * 32 + mb * 16 + (lane >> 2) + hf * 8;
                int r = mt * 128 + m_loc;
                *(float2*)(out + ((long)r * TT + t) * HH + hbase) =
                    make_float2(hnb[mb][hf][0], hnb[mb][hf][1]);
                if (t == TT - 1) {
                    *(float2*)(out + BTH + (long)r * HH + hbase) =
                        make_float2(hnb[mb][hf][0], hnb[mb][hf][1]);
                    *(float2*)(out + BTH + BH + (long)r * HH + hbase) =
                        make_float2(creg[mb][hf][0], creg[mb][hf][1]);
                }
            }
        }
    }
}

// ---------------------------------------------------------------------------
extern "C" void kernel_launch(void* const* d_in, const int* in_sizes, int n_in,
                              void* d_out, int out_size) {
    const float* x  = (const float*)d_in[0];
    const float* h0 = (const float*)d_in[1];
    const float* c0 = (const float*)d_in[2];
    const float* Wx = (const float*)d_in[3];
    const float* Wh = (const float*)d_in[4];
    const float* b  = (const float*)d_in[5];
    float* out = (float*)d_out;

    cudaFuncSetAttribute(lstm_persist, cudaFuncAttributeMaxDynamicSharedMemorySize, DSMEM);

    transform_x<<<32768, 256>>>(x);
    {
        long total = (long)64 * NKT * B_IMG;
        transform_W<<<(int)((total + 255) / 256), 256>>>(Wx, Wh);
    }
    init_state<<<1024, 256>>>(h0, c0);

    lstm_persist<<<dim3(64, 2), 256, DSMEM>>>(b, out);
}